// round 15
// baseline (speedup 1.0000x reference)
#include <cuda_runtime.h>
#include <cooperative_groups.h>
#include <cstdint>

namespace cg = cooperative_groups;

#define H      16384
#define BATCH  512
#define INSZ   2048
#define KSEL   64
#define DECAY  0.95f

#define NCTA   8
#define TPB    512
#define HP     (H / NCTA)      // 2048 elements per CTA
#define CAP    1024            // global candidate cap
#define PCAP   512             // per-CTA candidate cap

__device__ float g_enc[(size_t)BATCH * H];   // 32 MB scratch (no-alloc rule)

// ---------------------------------------------------------------------------
__global__ void zero_out_kernel(float4* __restrict__ out, int n4) {
    int i = blockIdx.x * blockDim.x + threadIdx.x;
    if (i < n4) out[i] = make_float4(0.f, 0.f, 0.f, 0.f);
}

// ---------------------------------------------------------------------------
// fp32 GEMM  C[m][n] = sum_k A[m][k] * W[n][k]; 128x128 tile, BK=16
// (round-8 baseline version — unchanged, known quantity)
// ---------------------------------------------------------------------------
#define GBM 128
#define GBN 128
#define GBK 16

__global__ void __launch_bounds__(256) sgemm_nt_kernel(
    const float* __restrict__ A, const float* __restrict__ W)
{
    __shared__ float As[GBK][GBM];
    __shared__ float Bs[GBK][GBN];

    const int bn = blockIdx.x * GBN, bm = blockIdx.y * GBM;
    const int tid = threadIdx.x, tx = tid & 15, ty = tid >> 4;

    float acc[8][8];
#pragma unroll
    for (int i = 0; i < 8; i++)
#pragma unroll
        for (int j = 0; j < 8; j++) acc[i][j] = 0.f;

    for (int k0 = 0; k0 < INSZ; k0 += GBK) {
#pragma unroll
        for (int l = 0; l < 2; l++) {
            int q = tid + 256 * l, row = q >> 2, kk = (q & 3) * 4;
            float4 v = *(const float4*)&A[(bm + row) * INSZ + k0 + kk];
            As[kk][row] = v.x; As[kk + 1][row] = v.y;
            As[kk + 2][row] = v.z; As[kk + 3][row] = v.w;
        }
#pragma unroll
        for (int l = 0; l < 2; l++) {
            int q = tid + 256 * l, row = q >> 2, kk = (q & 3) * 4;
            float4 v = *(const float4*)&W[(bn + row) * INSZ + k0 + kk];
            Bs[kk][row] = v.x; Bs[kk + 1][row] = v.y;
            Bs[kk + 2][row] = v.z; Bs[kk + 3][row] = v.w;
        }
        __syncthreads();
#pragma unroll
        for (int k = 0; k < GBK; k++) {
            float a[8], b[8];
#pragma unroll
            for (int i = 0; i < 8; i++) a[i] = As[k][ty * 8 + i];
#pragma unroll
            for (int i = 0; i < 8; i++) b[i] = Bs[k][tx * 8 + i];
#pragma unroll
            for (int i = 0; i < 8; i++)
#pragma unroll
                for (int j = 0; j < 8; j++)
                    acc[i][j] = fmaf(a[i], b[j], acc[i][j]);
        }
        __syncthreads();
    }
#pragma unroll
    for (int i = 0; i < 8; i++) {
        int m = bm + ty * 8 + i;
#pragma unroll
        for (int j = 0; j < 8; j += 4)
            *(float4*)&g_enc[(size_t)m * H + bn + tx * 8 + j] =
                make_float4(acc[i][j], acc[i][j+1], acc[i][j+2], acc[i][j+3]);
    }
}

// ---------------------------------------------------------------------------
// Cluster-parallel scan, 1 cluster.sync per row (steady state).
// 8 CTAs x 512 threads; thread tid owns indices base+4*tid+c and their inhib.
// Candidate key: (r_bits<<32) | (e>0)<<16 | (16383 - idx)  (same as r12/r13).
// Speculative publish: candidates+counts+poscount are exported BEFORE
// acceptance; one cluster.sync makes them visible; rejection is cluster-
// uniform so rejected buffers are never read. Row-parity double buffers +
// the <=1-sync skew bound make reuse safe.
// Fill (total-order top_k, -0.0 < +0.0): selected positives, then
// non-selected e>0 ascending, then non-selected e<0 ascending; global fill
// prefixes derived locally from published poscounts + redundant selkeys.
// ---------------------------------------------------------------------------
__global__ void __launch_bounds__(TPB, 1) __cluster_dims__(NCTA, 1, 1)
scan_kernel(float* __restrict__ out)
{
    // export blocks (read remotely by peers): [row parity]
    __shared__ unsigned long long sx_ckey[2][PCAP];
    __shared__ int      sx_cnt[2][2];                 // [row parity][iter parity]
    __shared__ int      sx_pos[2];                    // per-row positive count
    __shared__ unsigned sx_rmax;
    // local working storage
    __shared__ unsigned long long s_all[CAP];
    __shared__ unsigned long long s_selkey[KSEL];
    __shared__ unsigned s_selbit[HP / 32];            // 64 words
    __shared__ unsigned s_w[16], s_w2[16];
    __shared__ int      s_mir[16];                    // [0..7]=cnt, [8..15]=pos

    cg::cluster_group cluster = cg::this_cluster();
    const int myrank = (int)cluster.block_rank();
    const int tid = threadIdx.x, lane = tid & 31, wp = tid >> 5;
    const unsigned full = 0xffffffffu;
    const unsigned lt = (1u << lane) - 1u;
    const int base = myrank * HP;

    float inhib[4] = {0.f, 0.f, 0.f, 0.f};
    float T_ws = -1.f;

    float4 vcur = *(const float4*)(g_enc + base + 4 * tid);   // row 0

    for (int row = 0; row < BATCH; row++) {
        float* orow = out + (size_t)row * H;
        const int pb = row & 1;

        if (tid < HP / 32) s_selbit[tid] = 0u;

        // ---- refracted + pmask + local positive count ----
        float e[4] = {vcur.x, vcur.y, vcur.z, vcur.w};
        float r[4];
        unsigned pmask = 0;
#pragma unroll
        for (int c = 0; c < 4; c++) {
            r[c] = fabsf(e[c]) * (1.0f - inhib[c]);
            pmask |= (unsigned)(e[c] > 0.f) << c;
        }
        {
            int pc = __popc(pmask);
#pragma unroll
            for (int o = 16; o > 0; o >>= 1) pc += __shfl_xor_sync(full, pc, o);
            if (lane == 0) s_w[wp] = (unsigned)pc;
        }
        __syncthreads();
        {
            int tot = 0;
#pragma unroll
            for (int w = 0; w < 16; w++) tot += (int)s_w[w];
            if (tid == 0) sx_pos[pb] = tot;
        }

        float T = T_ws;
        float Tlo = 0.f, Thi = 0.f;
        bool haveHi = false;

        // ---- rmax path (row 0 only; uniform) ----
        if (!(T > 0.f)) {
            unsigned m = 0;
#pragma unroll
            for (int c = 0; c < 4; c++)
                m = max(m, __float_as_uint(fmaxf(r[c], 0.f)));   // clamp FIRST
            m = __reduce_max_sync(full, m);
            if (lane == 0) s_w2[wp] = m;
            __syncthreads();
            unsigned mm = 0;
#pragma unroll
            for (int w = 0; w < 16; w++) mm = max(mm, s_w2[w]);
            if (tid == 0) sx_rmax = mm;
            cluster.sync();
            if (tid < NCTA)
                s_mir[tid] = (int)*cluster.map_shared_rank(&sx_rmax, tid);
            __syncthreads();
            unsigned g = 0;
#pragma unroll
            for (int c = 0; c < NCTA; c++) g = max(g, (unsigned)s_mir[c]);
            float rmax = __uint_as_float(g);
            Thi = rmax; haveHi = true; T = 0.5f * rmax;
        }

        // ---- bisection with speculative candidate publish; 1 sync/iter ----
        int M, it = 0;
        for (;;) {
            int wc = 0;
#pragma unroll
            for (int c = 0; c < 4; c++)
                wc += __popc(__ballot_sync(full, r[c] > T));
            if (lane == 0) s_w[wp] = (unsigned)wc;
            __syncthreads();
            int tot = 0, wbase = 0;
#pragma unroll
            for (int w = 0; w < 16; w++) {
                int x = (int)s_w[w];
                if (w < wp) wbase += x;
                tot += x;
            }
            // speculative write of candidates at exclusive offsets
            {
                int cum = 0;
#pragma unroll
                for (int c = 0; c < 4; c++) {
                    unsigned bal = __ballot_sync(full, r[c] > T);
                    if (r[c] > T) {
                        int pos = wbase + cum + __popc(bal & lt);
                        if (pos < PCAP) {
                            unsigned idx = (unsigned)(base + 4 * tid + c);
                            sx_ckey[pb][pos] =
                                ((unsigned long long)__float_as_uint(r[c]) << 32)
                                | (((pmask >> c) & 1u) << 16) | (16383u - idx);
                        }
                    }
                    cum += __popc(bal);
                }
            }
            if (tid == 0) sx_cnt[pb][it & 1] = tot;
            if (it == 0 && row + 1 < BATCH)       // prefetch next row early
                vcur = *(const float4*)(g_enc + (size_t)(row + 1) * H + base + 4 * tid);
            cluster.sync();
            if (tid < NCTA)
                s_mir[tid] = *cluster.map_shared_rank(&sx_cnt[pb][it & 1], tid);
            else if (tid < 2 * NCTA)
                s_mir[tid] = *cluster.map_shared_rank(&sx_pos[pb], tid - NCTA);
            __syncthreads();
            M = 0; int maxloc = 0;
#pragma unroll
            for (int c = 0; c < NCTA; c++) {
                int x = s_mir[c];
                M += x; maxloc = max(maxloc, x);
            }
            if (M >= KSEL && M <= CAP && maxloc <= PCAP) break;
            if (M > CAP || maxloc > PCAP) {
                Tlo = T; T = haveHi ? 0.5f * (Tlo + Thi) : T * 2.0f;
            } else {
                Thi = T; haveHi = true; T = 0.5f * (Tlo + Thi);
            }
            it++;
        }

        // ---- parallel flat gather: one remote load per candidate slot ----
        {
            int off[NCTA + 1];
            off[0] = 0;
#pragma unroll
            for (int c = 0; c < NCTA; c++) off[c + 1] = off[c] + s_mir[c];
            for (int g = tid; g < M; g += TPB) {
                int c = 0;
#pragma unroll
                for (int q = 1; q < NCTA; q++) c += (g >= off[q]);
                const unsigned long long* rp =
                    cluster.map_shared_rank(&sx_ckey[pb][0], c);
                s_all[g] = rp[g - off[c]];
            }
        }
        __syncthreads();

        // ---- redundant exact rank selection (identical on all CTAs) ----
        for (int tt = tid; tt < M; tt += TPB) {
            unsigned long long k = s_all[tt];
            int rank = 0;
            for (int d = 0; d < M; d++) rank += (s_all[d] > k);
            if (rank < KSEL) {
                s_selkey[rank] = k;
                unsigned idx = 16383u - ((unsigned)k & 0x3FFFu);
                if ((int)(idx >> 11) == myrank) {     // owner emits
                    unsigned l = idx - (unsigned)base;
                    atomicOr(&s_selbit[l >> 5], 1u << (l & 31));
                    if ((k >> 16) & 1ull) orow[idx] = 1.0f;
                }
            }
        }
        __syncthreads();

        // ---- selkey sweep: p, per-CTA sel counts (packed), inhib, T_ws ----
        int p = 0;
        unsigned long long selcnt_pk = 0ull, selpos_pk = 0ull;
#pragma unroll
        for (int c = 0; c < 4; c++) inhib[c] *= DECAY;
        for (int s = 0; s < KSEL; s++) {
            unsigned long long k = s_selkey[s];
            unsigned idx = 16383u - ((unsigned)k & 0x3FFFu);
            int c = (int)(idx >> 11);
            int posb = (int)((k >> 16) & 1ull);
            p += posb;
            selcnt_pk += 1ull << (8 * c);
            selpos_pk += (unsigned long long)posb << (8 * c);
            int l = (int)idx - base;
            if ((l >> 2) == tid)                 // foreign l never matches
                inhib[l & 3] += 1.0f;
        }
        T_ws = __uint_as_float((unsigned)(s_selkey[KSEL - 1] >> 32)) * 0.85f;

        // ---- fill, no cluster sync: prefixes from sx_pos mirror + packs ----
        if (p < KSEL) {
            int start0 = p, sumf0 = 0, start1b = 0;
#pragma unroll
            for (int c = 0; c < NCTA; c++) {
                int posc = s_mir[8 + c];
                int scc  = (int)((selcnt_pk >> (8 * c)) & 255ull);
                int spc  = (int)((selpos_pk >> (8 * c)) & 255ull);
                int f0 = posc - spc;
                int f1 = (HP - posc) - (scc - spc);
                if (c < myrank) { start0 += f0; start1b += f1; }
                sumf0 += f0;
            }
            int start1 = p + sumf0 + start1b;

            unsigned cb0 = 0, cb1 = 0;
#pragma unroll
            for (int c = 0; c < 4; c++) {
                int l = 4 * tid + c;
                bool sel = (s_selbit[l >> 5] >> (l & 31)) & 1u;
                bool pbit = (pmask >> c) & 1u;
                cb0 |= (unsigned)(!sel &&  pbit) << c;
                cb1 |= (unsigned)(!sel && !pbit) << c;
            }
            int n0 = __popc(cb0), n1 = __popc(cb1);
            int e0 = n0, e1 = n1;
#pragma unroll
            for (int o = 1; o < 32; o <<= 1) {
                int v0 = __shfl_up_sync(full, e0, o);
                int v1 = __shfl_up_sync(full, e1, o);
                if (lane >= o) { e0 += v0; e1 += v1; }
            }
            int i0 = e0 - n0, i1 = e1 - n1;
            if (lane == 31) { s_w[wp] = (unsigned)e0; s_w2[wp] = (unsigned)e1; }
            __syncthreads();
            int wb0 = 0, wb1 = 0;
#pragma unroll
            for (int w = 0; w < 16; w++) {
                if (w < wp) { wb0 += (int)s_w[w]; wb1 += (int)s_w2[w]; }
            }
            int pos = start0 + wb0 + i0;
            if (start0 < KSEL) {
#pragma unroll
                for (int c = 0; c < 4; c++)
                    if ((cb0 >> c) & 1u) {
                        if (pos < KSEL) orow[base + 4 * tid + c] = 1.0f;
                        pos++;
                    }
            }
            pos = start1 + wb1 + i1;
            if (start1 < KSEL) {
#pragma unroll
                for (int c = 0; c < 4; c++)
                    if ((cb1 >> c) & 1u) {
                        if (pos < KSEL) orow[base + 4 * tid + c] = 1.0f;
                        pos++;
                    }
            }
        }
        __syncthreads();   // protect selbit/s_w/s_all reuse next row
    }
}

// ---------------------------------------------------------------------------
extern "C" void kernel_launch(void* const* d_in, const int* in_sizes, int n_in,
                              void* d_out, int out_size)
{
    const float* inputs = (const float*)d_in[0];   // [512, 2048]
    const float* W      = (const float*)d_in[1];   // [16384, 2048]
    float* out          = (float*)d_out;           // [512, 16384]

    const int n4 = (BATCH * H) / 4;
    zero_out_kernel<<<(n4 + 255) / 256, 256>>>((float4*)out, n4);

    dim3 ggrid(H / GBN, BATCH / GBM);              // (128, 4)
    sgemm_nt_kernel<<<ggrid, 256>>>(inputs, W);

    scan_kernel<<<NCTA, TPB>>>(out);               // 1 cluster of 8 CTAs
}

// round 16
// speedup vs baseline: 1.5611x; 1.5611x over previous
#include <cuda_runtime.h>
#include <cstdint>

#define H      16384
#define BATCH  512
#define INSZ   2048
#define KSEL   64
#define DECAY  0.95f

#define NTH    1024        // scan threads
#define CCAP   512         // candidate capacity per row

typedef unsigned long long ull;

__device__ float g_enc[(size_t)BATCH * H];       // 32 MB
__device__ ull   g_cand[(size_t)BATCH * CCAP];   // 2 MB  (e_bits<<32 | idx)
__device__ int   g_ccnt[BATCH];
__device__ float g_bound[BATCH];
__device__ int   g_pcnt[BATCH * 32];             // per-512-block positive counts

// ---------------------------------------------------------------------------
__global__ void zero_out_kernel(float4* __restrict__ out, int n4) {
    int i = blockIdx.x * blockDim.x + threadIdx.x;
    if (i < n4) out[i] = make_float4(0.f, 0.f, 0.f, 0.f);
}

// ---------------------------------------------------------------------------
// fp32 GEMM (round-8 baseline — unchanged, known quantity)
// ---------------------------------------------------------------------------
#define GBM 128
#define GBN 128
#define GBK 16

__global__ void __launch_bounds__(256) sgemm_nt_kernel(
    const float* __restrict__ A, const float* __restrict__ W)
{
    __shared__ float As[GBK][GBM];
    __shared__ float Bs[GBK][GBN];

    const int bn = blockIdx.x * GBN, bm = blockIdx.y * GBM;
    const int tid = threadIdx.x, tx = tid & 15, ty = tid >> 4;

    float acc[8][8];
#pragma unroll
    for (int i = 0; i < 8; i++)
#pragma unroll
        for (int j = 0; j < 8; j++) acc[i][j] = 0.f;

    for (int k0 = 0; k0 < INSZ; k0 += GBK) {
#pragma unroll
        for (int l = 0; l < 2; l++) {
            int q = tid + 256 * l, row = q >> 2, kk = (q & 3) * 4;
            float4 v = *(const float4*)&A[(bm + row) * INSZ + k0 + kk];
            As[kk][row] = v.x; As[kk + 1][row] = v.y;
            As[kk + 2][row] = v.z; As[kk + 3][row] = v.w;
        }
#pragma unroll
        for (int l = 0; l < 2; l++) {
            int q = tid + 256 * l, row = q >> 2, kk = (q & 3) * 4;
            float4 v = *(const float4*)&W[(bn + row) * INSZ + k0 + kk];
            Bs[kk][row] = v.x; Bs[kk + 1][row] = v.y;
            Bs[kk + 2][row] = v.z; Bs[kk + 3][row] = v.w;
        }
        __syncthreads();
#pragma unroll
        for (int k = 0; k < GBK; k++) {
            float a[8], b[8];
#pragma unroll
            for (int i = 0; i < 8; i++) a[i] = As[k][ty * 8 + i];
#pragma unroll
            for (int i = 0; i < 8; i++) b[i] = Bs[k][tx * 8 + i];
#pragma unroll
            for (int i = 0; i < 8; i++)
#pragma unroll
                for (int j = 0; j < 8; j++)
                    acc[i][j] = fmaf(a[i], b[j], acc[i][j]);
        }
        __syncthreads();
    }
#pragma unroll
    for (int i = 0; i < 8; i++) {
        int m = bm + ty * 8 + i;
#pragma unroll
        for (int j = 0; j < 8; j += 4)
            *(float4*)&g_enc[(size_t)m * H + bn + tx * 8 + j] =
                make_float4(acc[i][j], acc[i][j+1], acc[i][j+2], acc[i][j+3]);
    }
}

// ---------------------------------------------------------------------------
// Precompute (parallel over rows): per row, candidate set {|e| > T} with
// |S| in [192,448] (forced-accept [64,512]), bound = T, and per-512-block
// positive counts. Candidates carry raw e bits + idx; order arbitrary.
// ---------------------------------------------------------------------------
__global__ void __launch_bounds__(512) precomp_kernel()
{
    const int row = blockIdx.x;
    const float* erow = g_enc + (size_t)row * H;
    __shared__ int   s_pb[32];
    __shared__ int   s_w[16];
    __shared__ float s_red[16];
    __shared__ int   s_cnt;

    const int tid = threadIdx.x, lane = tid & 31, wp = tid >> 5;
    const unsigned full = 0xffffffffu;

    if (tid < 32) s_pb[tid] = 0;
    __syncthreads();

    float va[32];
    float mx = 0.f;
#pragma unroll
    for (int jj = 0; jj < 8; jj++) {
        float4 v = *(const float4*)(erow + 2048 * jj + 4 * tid);
        va[4*jj+0] = v.x; va[4*jj+1] = v.y; va[4*jj+2] = v.z; va[4*jj+3] = v.w;
        mx = fmaxf(mx, fmaxf(fmaxf(fabsf(v.x), fabsf(v.y)),
                             fmaxf(fabsf(v.z), fabsf(v.w))));
        int pc = (v.x > 0.f) + (v.y > 0.f) + (v.z > 0.f) + (v.w > 0.f);
        pc = __reduce_add_sync(full, pc);
        if (lane == 0) atomicAdd(&s_pb[4 * jj + (wp >> 2)], pc);
    }
#pragma unroll
    for (int o = 16; o > 0; o >>= 1) mx = fmaxf(mx, __shfl_xor_sync(full, mx, o));
    if (lane == 0) s_red[wp] = mx;
    __syncthreads();
    float rmax = 0.f;
#pragma unroll
    for (int w = 0; w < 16; w++) rmax = fmaxf(rmax, s_red[w]);

    float Tlo = 0.f, Thi = rmax, T = 0.5f * rmax;
    int M = 0;
    bool ok = false;
    for (int it = 0; it < 64; it++) {
        int c = 0;
#pragma unroll
        for (int u = 0; u < 32; u++) c += (fabsf(va[u]) > T);
        c = __reduce_add_sync(full, c);
        if (lane == 0) s_w[wp] = c;
        __syncthreads();
        M = 0;
#pragma unroll
        for (int w = 0; w < 16; w++) M += s_w[w];
        int lo = it < 40 ? 192 : 64;
        int hi = it < 40 ? 448 : 512;
        if (M >= lo && M <= hi) { ok = true; break; }
        if (M > hi) Tlo = T; else Thi = T;
        T = 0.5f * (Tlo + Thi);
        __syncthreads();                        // s_w reuse
    }

    if (ok) {
        if (tid == 0) s_cnt = 0;
        __syncthreads();
#pragma unroll
        for (int u = 0; u < 32; u++) {
            if (fabsf(va[u]) > T) {
                int pos = atomicAdd(&s_cnt, 1);
                int idx = 2048 * (u >> 2) + 4 * tid + (u & 3);
                g_cand[(size_t)row * CCAP + pos] =
                    ((ull)__float_as_uint(va[u]) << 32) | (unsigned)idx;
            }
        }
    }
    if (tid == 0) { g_ccnt[row] = ok ? M : 0; g_bound[row] = T; }
    if (tid < 32) g_pcnt[row * 32 + tid] = s_pb[tid];
}

// ---------------------------------------------------------------------------
// Sequential scan, single CTA, candidate-set fast path.
// Dense inhibition lives in smem (64KB). Selection keys identical to the
// passing r12 kernel: (max(r,0)_bits<<32) | (e>0)<<16 | (16383 - idx).
// Validity: excluded units have r <= |e| <= bound; accept iff v64_r > bound,
// else full-row fallback (float-only reductions; negatives never bit-compared).
// Fill (total-order top_k, -0.0 < +0.0): selected positives, then
// non-selected e>0 ascending, then non-selected e<=0 ascending — resolved by
// block-walk over precomputed positive counts; only boundary blocks loaded.
// ---------------------------------------------------------------------------
__global__ void __launch_bounds__(NTH, 1) scan_kernel(float* __restrict__ out)
{
    extern __shared__ char smem_raw[];
    float*    s_inhib  = (float*)smem_raw;                    // 65536 B
    ull*      s_k      = (ull*)(smem_raw + 65536);            // 8192 B
    ull*      s_sel    = (ull*)(smem_raw + 73728);            // 512 B
    unsigned* s_selbit = (unsigned*)(smem_raw + 74240);       // 2048 B
    int*      s_pb     = (int*)(smem_raw + 76288);            // 128 B
    int*      s_spb    = (int*)(smem_raw + 76416);
    int*      s_scb    = (int*)(smem_raw + 76544);
    int*      s_w      = (int*)(smem_raw + 76672);            // 128 B
    float*    s_fred   = (float*)(smem_raw + 76800);          // 128 B

    const int tid = threadIdx.x, lane = tid & 31, wp = tid >> 5;
    const unsigned full = 0xffffffffu;
    const unsigned lt = (1u << lane) - 1u;

#pragma unroll
    for (int j = 0; j < 16; j++) s_inhib[tid + NTH * j] = 0.f;
    if (tid < 512) s_selbit[tid] = 0u;
    __syncthreads();

    for (int row = 0; row < BATCH; row++) {
        const float* erow = g_enc + (size_t)row * H;
        float* orow = out + (size_t)row * H;

        int Ccnt = g_ccnt[row];
        float bound = g_bound[row];
        bool fb = (Ccnt < KSEL);

        if (!fb) {
            // ---- fast path: rank only the precomputed candidates ----
            if (tid < Ccnt) {
                ull k = g_cand[(size_t)row * CCAP + tid];
                unsigned idx = (unsigned)(k & 0xFFFFFFFFull);
                unsigned eb  = (unsigned)(k >> 32);
                float ae = __uint_as_float(eb & 0x7FFFFFFFu);
                float r  = ae * (1.0f - s_inhib[idx]);        // pre-decay inhib
                unsigned pbit = (eb >> 31) ^ 1u;              // e>0 (|e|>T>0)
                float rc = fmaxf(r, 0.0f);                    // clamp: key order
                s_k[tid] = ((ull)__float_as_uint(rc) << 32)
                           | (pbit << 16) | (16383u - idx);
            }
            __syncthreads();
            if (tid < Ccnt) {
                ull k = s_k[tid];
                int rank = 0;
                for (int d = 0; d < Ccnt; d++) rank += (s_k[d] > k);
                if (rank < KSEL) s_sel[rank] = k;
            }
            __syncthreads();
            float v64r = __uint_as_float((unsigned)(s_sel[KSEL - 1] >> 32));
            fb = !(v64r > bound);                             // strict: ties -> fb
        }

        if (fb) {
            // ---- full-row fallback (expected ~never; must be exact) ----
            float e[16], r[16];
#pragma unroll
            for (int jj = 0; jj < 4; jj++) {
                float4 v = *(const float4*)(erow + 4096 * jj + 4 * tid);
                e[4*jj+0] = v.x; e[4*jj+1] = v.y; e[4*jj+2] = v.z; e[4*jj+3] = v.w;
            }
            float mx = 0.f;
#pragma unroll
            for (int u = 0; u < 16; u++) {
                int idx = 4096 * (u >> 2) + 4 * tid + (u & 3);
                r[u] = fabsf(e[u]) * (1.0f - s_inhib[idx]);
                mx = fmaxf(mx, r[u]);                         // float max, safe
            }
#pragma unroll
            for (int o = 16; o > 0; o >>= 1)
                mx = fmaxf(mx, __shfl_xor_sync(full, mx, o));
            if (lane == 0) s_fred[wp] = mx;
            __syncthreads();
            float rmax = 0.f;
#pragma unroll
            for (int w = 0; w < 32; w++) rmax = fmaxf(rmax, s_fred[w]);

            float Tlo = 0.f, Thi = rmax, T = 0.5f * rmax;
            int M, wbase;
            for (;;) {
                int c = 0;
#pragma unroll
                for (int u = 0; u < 16; u++) c += (r[u] > T);
                c = __reduce_add_sync(full, c);
                if (lane == 0) s_w[wp] = c;
                __syncthreads();
                wbase = 0; M = 0;
#pragma unroll
                for (int w = 0; w < 32; w++) {
                    int x = s_w[w];
                    if (w < wp) wbase += x;
                    M += x;
                }
                if (M >= KSEL && M <= NTH) break;
                if (M > NTH) Tlo = T; else Thi = T;
                T = 0.5f * (Tlo + Thi);
                __syncthreads();
            }
            int base = wbase;
#pragma unroll
            for (int u = 0; u < 16; u++) {
                unsigned bal = __ballot_sync(full, r[u] > T);
                if (r[u] > T) {
                    int pos = base + __popc(bal & lt);
                    unsigned idx = (unsigned)(4096 * (u >> 2) + 4 * tid + (u & 3));
                    unsigned pbit = (e[u] > 0.f) ? 1u : 0u;
                    s_k[pos] = ((ull)__float_as_uint(r[u]) << 32)
                               | (pbit << 16) | (16383u - idx);
                }
                base += __popc(bal);
            }
            __syncthreads();
            if (tid < M) {
                ull k = s_k[tid];
                int rank = 0;
                for (int d = 0; d < M; d++) rank += (s_k[d] > k);
                if (rank < KSEL) s_sel[rank] = k;
            }
            __syncthreads();
        }

        // ---- emit: selbit, per-block selected counts, positive outputs ----
        if (tid < 32) { s_spb[tid] = 0; s_scb[tid] = 0; }
        __syncthreads();
        int p = 0;
        for (int s = 0; s < KSEL; s++) p += (int)((s_sel[s] >> 16) & 1ull);
        if (tid < KSEL) {
            ull k = s_sel[tid];
            unsigned idx = 16383u - ((unsigned)k & 0x3FFFu);
            atomicOr(&s_selbit[idx >> 5], 1u << (idx & 31));
            atomicAdd(&s_scb[idx >> 9], 1);
            if ((k >> 16) & 1ull) {
                atomicAdd(&s_spb[idx >> 9], 1);
                orow[idx] = 1.0f;
            }
        }
        __syncthreads();          // emit done; also orders inhib reads < decay

        // ---- decay sweep, then +1 for selected (r12 rounding order) ----
#pragma unroll
        for (int j = 0; j < 16; j++) {
            int ii = tid + NTH * j;
            s_inhib[ii] *= DECAY;
        }
        __syncthreads();
        if (tid < KSEL) {
            unsigned idx = 16383u - ((unsigned)s_sel[tid] & 0x3FFFu);
            s_inhib[idx] += 1.0f;                    // unique indices
        }

        // ---- fill via block-walk (only boundary blocks loaded) ----
        if (p < KSEL) {
            if (tid < 32) s_pb[tid] = g_pcnt[row * 32 + tid];
            __syncthreads();
            int cum = p;
            for (int pass = 0; pass < 2 && cum < KSEL; pass++) {
                for (int b = 0; b < 32; b++) {
                    int F = (pass == 0)
                          ? (s_pb[b] - s_spb[b])
                          : ((512 - s_pb[b]) - (s_scb[b] - s_spb[b]));
                    if (F > 0) {
                        if (cum < KSEL) {
                            bool cand = false;
                            if (tid < 512) {
                                int idx = 512 * b + tid;
                                float ev = __ldg(erow + idx);
                                bool sel = (s_selbit[idx >> 5] >> (idx & 31)) & 1u;
                                bool pos = (ev > 0.f);
                                cand = !sel && (pass == 0 ? pos : !pos);
                            }
                            unsigned bal = __ballot_sync(full, cand);
                            int pre = __popc(bal & lt);
                            if (lane == 0) s_w[wp] = __popc(bal);
                            __syncthreads();
                            int gpre = 0;
#pragma unroll
                            for (int w = 0; w < 32; w++)
                                if (w < wp) gpre += s_w[w];
                            if (cand) {
                                int pos2 = cum + gpre + pre;
                                if (pos2 < KSEL) orow[512 * b + tid] = 1.0f;
                            }
                            __syncthreads();       // s_w reuse
                        }
                        cum += F;
                        if (cum >= KSEL) break;
                    }
                }
            }
        }

        // ---- end of row: clear selbit; make inhib updates visible ----
        __syncthreads();
        if (tid < 512) s_selbit[tid] = 0u;
        __syncthreads();
    }
}

// ---------------------------------------------------------------------------
extern "C" void kernel_launch(void* const* d_in, const int* in_sizes, int n_in,
                              void* d_out, int out_size)
{
    const float* inputs = (const float*)d_in[0];   // [512, 2048]
    const float* W      = (const float*)d_in[1];   // [16384, 2048]
    float* out          = (float*)d_out;           // [512, 16384]

    static int smem_set = 0;
    if (!smem_set) {
        cudaFuncSetAttribute(scan_kernel,
                             cudaFuncAttributeMaxDynamicSharedMemorySize, 81920);
        smem_set = 1;
    }

    const int n4 = (BATCH * H) / 4;
    zero_out_kernel<<<(n4 + 255) / 256, 256>>>((float4*)out, n4);

    dim3 ggrid(H / GBN, BATCH / GBM);              // (128, 4)
    sgemm_nt_kernel<<<ggrid, 256>>>(inputs, W);

    precomp_kernel<<<BATCH, 512>>>();

    scan_kernel<<<1, NTH, 81920>>>(out);
}